// round 16
// baseline (speedup 1.0000x reference)
#include <cuda_runtime.h>
#include <cuda_fp16.h>
#include <cstdint>

#define N_NODES 100000
#define N_EDGES 1600000
#define D 128
#define N_PANELS (N_NODES / 16)          // 6250, exact (100000 = 6250*16)
#define SCAN_BLK 1024
#define N_SCAN_BLOCKS ((N_NODES + SCAN_BLK - 1) / SCAN_BLK)   // 98

// ---------------------------------------------------------------------------
// Device scratch
// ---------------------------------------------------------------------------
__device__ int    g_cnt [N_NODES];
__device__ int    g_cur [N_NODES];
__device__ int    g_off [N_NODES + 1];   // block-local exclusive scan
__device__ int    g_bsum[128];           // block totals -> scanned in-place
__device__ int    g_scan_ctr;            // last-block detector
__device__ float4 g_edata[N_EDGES];      // {eid, src, w, pad}
__device__ __half g_nh [(size_t)N_NODES * D];   // nfeat fp16 (25.6 MB)
// A in mma-fragment layout (fp16): [panel][ks(16)][lane(32)] -> uint4
__device__ uint4  g_xh4[(size_t)N_PANELS * 512];
// W in fragment layout (fp16): [npp(8)][ks(16)][lane(32)][word(4)]
__device__ uint32_t g_wh32[16384];

// ---------------------------------------------------------------------------
// helpers
// ---------------------------------------------------------------------------
__device__ __forceinline__ int off_at(int i) {        // final CSR offset
    return g_off[i] + g_bsum[i >> 10];
}
__device__ __forceinline__ uint32_t hpair(float a, float b) {
    __half2 t = __floats2half2_rn(a, b);
    return *reinterpret_cast<uint32_t*>(&t);
}
__device__ __forceinline__ float4 h4_to_f4(uint2 h) {
    float2 a = __half22float2(*reinterpret_cast<__half2*>(&h.x));
    float2 b = __half22float2(*reinterpret_cast<__half2*>(&h.y));
    return make_float4(a.x, a.y, b.x, b.y);
}
__device__ __forceinline__ void mma_f16(float* d, const uint32_t* a,
                                        uint32_t b0, uint32_t b1) {
    asm volatile(
        "mma.sync.aligned.m16n8k16.row.col.f32.f16.f16.f32 "
        "{%0,%1,%2,%3}, {%4,%5,%6,%7}, {%8,%9}, {%0,%1,%2,%3};"
        : "+f"(d[0]), "+f"(d[1]), "+f"(d[2]), "+f"(d[3])
        : "r"(a[0]), "r"(a[1]), "r"(a[2]), "r"(a[3]), "r"(b0), "r"(b1));
}

// ---------------------------------------------------------------------------
// K0: fused setup — zero counters, nfeat->fp16, dst histogram, W->fragments.
// grid covers 3.2M threads.
// ---------------------------------------------------------------------------
__global__ __launch_bounds__(256) void k_setup(const float* __restrict__ nf,
                                               const int*   __restrict__ dst,
                                               const float* __restrict__ Wn,
                                               const float* __restrict__ We) {
    const int i = blockIdx.x * blockDim.x + threadIdx.x;

    if (i == 0) g_scan_ctr = 0;
    if (i < N_NODES) { g_cnt[i] = 0; g_cur[i] = 0; }

    if (i < N_NODES * (D / 4)) {            // nfeat -> fp16 (3.2M threads)
        const float4 v = __ldg(reinterpret_cast<const float4*>(nf) + i);
        uint2 h;
        h.x = hpair(v.x, v.y);
        h.y = hpair(v.z, v.w);
        reinterpret_cast<uint2*>(g_nh)[i] = h;
    }

    if (i < 16384) {                        // W -> fp16 fragment image
        const int e    = i >> 2;
        const int word = i & 3;
        const int npp  = e >> 9;
        const int rem  = e & 511;
        const int ks   = rem >> 5;
        const int lane = rem & 31;
        const int gid  = lane >> 2;
        const int tig  = lane & 3;
        const int col  = npp * 16 + (word >> 1) * 8 + gid;
        const int k    = ks * 16 + (word & 1) * 8 + tig * 2;
        float v0, v1;
        if (k < 128) { v0 = __ldg(Wn + col * 128 + k);       v1 = __ldg(Wn + col * 128 + k + 1); }
        else         { v0 = __ldg(We + col * 128 + k - 128); v1 = __ldg(We + col * 128 + k - 127); }
        g_wh32[i] = hpair(v0, v1);
    }
}

// histogram must run AFTER all g_cnt zeroing is complete -> separate kernel
__global__ __launch_bounds__(256) void k_hist(const int* __restrict__ dst) {
    int e = blockIdx.x * blockDim.x + threadIdx.x;
    if (e < N_EDGES) atomicAdd(&g_cnt[e < N_EDGES ? dst[e] : 0], e < N_EDGES ? 1 : 0);
}

// ---------------------------------------------------------------------------
// K1: block scan + last-block scans the block totals (replaces scan2).
// ---------------------------------------------------------------------------
__global__ __launch_bounds__(SCAN_BLK) void k_scan1() {
    __shared__ int warp_pfx[32];
    __shared__ int s_last;
    const int tid = threadIdx.x;
    const int i   = blockIdx.x * SCAN_BLK + tid;
    const int v   = (i < N_NODES) ? g_cnt[i] : 0;

    int x = v;
#pragma unroll
    for (int o = 1; o < 32; o <<= 1) {
        int y = __shfl_up_sync(0xffffffffu, x, o);
        if ((tid & 31) >= o) x += y;
    }
    if ((tid & 31) == 31) warp_pfx[tid >> 5] = x;
    __syncthreads();
    if (tid < 32) {
        int t = warp_pfx[tid];
        int s = t;
#pragma unroll
        for (int o = 1; o < 32; o <<= 1) {
            int y = __shfl_up_sync(0xffffffffu, s, o);
            if (tid >= o) s += y;
        }
        warp_pfx[tid] = s - t;
        if (tid == 31) g_bsum[blockIdx.x] = s;
    }
    __syncthreads();
    if (i <= N_NODES) g_off[i] = (x - v) + warp_pfx[tid >> 5];

    // publish, then the last-arriving block scans g_bsum in one warp
    __threadfence();
    if (tid == 0)
        s_last = (atomicAdd(&g_scan_ctr, 1) == gridDim.x - 1) ? 1 : 0;
    __syncthreads();
    if (s_last && tid < 32) {
        // lane j owns chunk [4j, 4j+4)
        int e0 = 0, e1 = 0, e2 = 0, e3 = 0;
        const int base = tid * 4;
        if (base + 0 < N_SCAN_BLOCKS) e0 = g_bsum[base + 0];
        if (base + 1 < N_SCAN_BLOCKS) e1 = g_bsum[base + 1];
        if (base + 2 < N_SCAN_BLOCKS) e2 = g_bsum[base + 2];
        if (base + 3 < N_SCAN_BLOCKS) e3 = g_bsum[base + 3];
        const int tot = e0 + e1 + e2 + e3;
        int p = tot;                         // inclusive warp scan of chunk totals
#pragma unroll
        for (int o = 1; o < 32; o <<= 1) {
            int y = __shfl_up_sync(0xffffffffu, p, o);
            if (tid >= o) p += y;
        }
        int pre = p - tot;                   // exclusive chunk prefix
        if (base + 0 < N_SCAN_BLOCKS) g_bsum[base + 0] = pre;
        if (base + 1 < N_SCAN_BLOCKS) g_bsum[base + 1] = pre + e0;
        if (base + 2 < N_SCAN_BLOCKS) g_bsum[base + 2] = pre + e0 + e1;
        if (base + 3 < N_SCAN_BLOCKS) g_bsum[base + 3] = pre + e0 + e1 + e2;
    }
}

// ---------------------------------------------------------------------------
// K2: permute edges into CSR order
// ---------------------------------------------------------------------------
__global__ __launch_bounds__(256) void k_perm(const int* __restrict__ src,
                                              const int* __restrict__ dst,
                                              const float* __restrict__ ew) {
    int e = blockIdx.x * blockDim.x + threadIdx.x;
    if (e >= N_EDGES) return;
    const int d   = dst[e];
    const int pos = off_at(d) + atomicAdd(&g_cur[d], 1);
    g_edata[pos] = make_float4(__int_as_float(e), __int_as_float(src[e]),
                               __ldg(ew + e), 0.f);
}

// ---------------------------------------------------------------------------
// K3: fused gather (R13). 512 threads = 16 warps = 1 panel (16 nodes).
// nfeat from the fp16 copy; efeat streamed fp32; fragment transpose via smem.
// ---------------------------------------------------------------------------
__global__ __launch_bounds__(512) void k_gather(const float* __restrict__ efeat) {
    __shared__ uint32_t h32[16][132];

    const int tid  = threadIdx.x;
    const int w    = tid >> 5;
    const int lane = tid & 31;
    const int pan  = blockIdx.x;
    const int n    = pan * 16 + w;            // always < N_NODES

    const int beg = off_at(n);
    const int end = off_at(n + 1);

    float4 accn = make_float4(0.f, 0.f, 0.f, 0.f);
    float4 acce = make_float4(0.f, 0.f, 0.f, 0.f);

    const uint2* nh2 = reinterpret_cast<const uint2*>(g_nh);

    int i = beg;
    for (; i + 3 < end; i += 4) {
        const float4 p0 = __ldg(g_edata + i + 0);
        const float4 p1 = __ldg(g_edata + i + 1);
        const float4 p2 = __ldg(g_edata + i + 2);
        const float4 p3 = __ldg(g_edata + i + 3);
        const int e0 = __float_as_int(p0.x), s0 = __float_as_int(p0.y);
        const int e1 = __float_as_int(p1.x), s1 = __float_as_int(p1.y);
        const int e2 = __float_as_int(p2.x), s2 = __float_as_int(p2.y);
        const int e3 = __float_as_int(p3.x), s3 = __float_as_int(p3.y);
        const float w0 = p0.z, w1 = p1.z, w2 = p2.z, w3 = p3.z;

        const float4 f0 = __ldg(reinterpret_cast<const float4*>(efeat + (size_t)e0 * D) + lane);
        const float4 f1 = __ldg(reinterpret_cast<const float4*>(efeat + (size_t)e1 * D) + lane);
        const float4 f2 = __ldg(reinterpret_cast<const float4*>(efeat + (size_t)e2 * D) + lane);
        const float4 f3 = __ldg(reinterpret_cast<const float4*>(efeat + (size_t)e3 * D) + lane);
        const uint2  h0 = __ldg(nh2 + (size_t)s0 * 32 + lane);
        const uint2  h1 = __ldg(nh2 + (size_t)s1 * 32 + lane);
        const uint2  h2 = __ldg(nh2 + (size_t)s2 * 32 + lane);
        const uint2  h3 = __ldg(nh2 + (size_t)s3 * 32 + lane);

        const float4 m0 = h4_to_f4(h0);
        const float4 m1 = h4_to_f4(h1);
        const float4 m2 = h4_to_f4(h2);
        const float4 m3 = h4_to_f4(h3);

        acce.x += (f0.x + f1.x) + (f2.x + f3.x);
        acce.y += (f0.y + f1.y) + (f2.y + f3.y);
        acce.z += (f0.z + f1.z) + (f2.z + f3.z);
        acce.w += (f0.w + f1.w) + (f2.w + f3.w);
        accn.x += (w0 * m0.x + w1 * m1.x) + (w2 * m2.x + w3 * m3.x);
        accn.y += (w0 * m0.y + w1 * m1.y) + (w2 * m2.y + w3 * m3.y);
        accn.z += (w0 * m0.z + w1 * m1.z) + (w2 * m2.z + w3 * m3.z);
        accn.w += (w0 * m0.w + w1 * m1.w) + (w2 * m2.w + w3 * m3.w);
    }
    for (; i < end; i++) {
        const float4 p = __ldg(g_edata + i);
        const int e = __float_as_int(p.x), s = __float_as_int(p.y);
        const float wt = p.z;
        const float4 f  = __ldg(reinterpret_cast<const float4*>(efeat + (size_t)e * D) + lane);
        const float4 mm = h4_to_f4(__ldg(nh2 + (size_t)s * 32 + lane));
        acce.x += f.x; acce.y += f.y; acce.z += f.z; acce.w += f.w;
        accn.x += wt * mm.x; accn.y += wt * mm.y; accn.z += wt * mm.z; accn.w += wt * mm.w;
    }

    const float deg = (float)(end - beg);
    const float rd1 = 1.f / (deg + 1.f);
    const float rd2 = 1.f / fmaxf(deg, 1.f);

    const float4 self = h4_to_f4(__ldg(nh2 + (size_t)n * 32 + lane));
    float x1[4], x2[4];
    x1[0] = (accn.x + 2.f * self.x) * rd1;
    x1[1] = (accn.y + 2.f * self.y) * rd1;
    x1[2] = (accn.z + 2.f * self.z) * rd1;
    x1[3] = (accn.w + 2.f * self.w) * rd1;
    x2[0] = acce.x * rd2; x2[1] = acce.y * rd2;
    x2[2] = acce.z * rd2; x2[3] = acce.w * rd2;

    {
        uint2 a;
        a.x = hpair(x1[0], x1[1]);  a.y = hpair(x1[2], x1[3]);
        *reinterpret_cast<uint2*>(&h32[w][2 * lane]) = a;
        uint2 b;
        b.x = hpair(x2[0], x2[1]);  b.y = hpair(x2[2], x2[3]);
        *reinterpret_cast<uint2*>(&h32[w][64 + 2 * lane]) = b;
    }
    __syncthreads();

    {
        const int ks  = w;
        const int gid = lane >> 2;
        const int tig = lane & 3;
        uint4 vh;
        vh.x = h32[gid    ][ks * 8 + tig];
        vh.y = h32[gid + 8][ks * 8 + tig];
        vh.z = h32[gid    ][ks * 8 + 4 + tig];
        vh.w = h32[gid + 8][ks * 8 + 4 + tig];
        const size_t eidx = ((size_t)pan * 16 + ks) * 32 + lane;
        g_xh4[eidx] = vh;
    }
}

// ---------------------------------------------------------------------------
// K4: fp16 HMMA GEMM, single pass. 256 threads = 8 warps.
// Block: 128 rows (8 panels) x 128 cols. Warp tile 32(M) x 64(N).
// ---------------------------------------------------------------------------
__global__ __launch_bounds__(256) void k_mgemm(const float* __restrict__ bn,
                                               const float* __restrict__ be,
                                               float* __restrict__ out) {
    const int bx   = blockIdx.x;
    const int tid  = threadIdx.x;
    const int w    = tid >> 5;
    const int lane = tid & 31;
    const int gid  = lane >> 2;
    const int tig  = lane & 3;
    const int warp_m = (w & 3) * 32;
    const int warp_n = (w >> 2) * 64;
    const int n0   = bx * 128;
    const int nppb = (w >> 2) * 4;

    float acc[2][8][4];
#pragma unroll
    for (int mt = 0; mt < 2; mt++)
#pragma unroll
        for (int nt = 0; nt < 8; nt++)
#pragma unroll
            for (int j = 0; j < 4; j++) acc[mt][nt][j] = 0.f;

    int  pan[2];
    bool pv[2];
#pragma unroll
    for (int mt = 0; mt < 2; mt++) {
        pan[mt] = bx * 8 + (w & 3) * 2 + mt;
        pv[mt]  = pan[mt] < N_PANELS;
    }

    const uint4* B4 = reinterpret_cast<const uint4*>(g_wh32);

    uint4 abuf[2][2];   // [buf][mt]
    auto loadA = [&](int ks, uint4* a_) {
#pragma unroll
        for (int mt = 0; mt < 2; mt++) {
            a_[mt] = make_uint4(0, 0, 0, 0);
            if (pv[mt])
                a_[mt] = __ldg(g_xh4 + ((size_t)(pan[mt] * 16 + ks) * 32 + lane));
        }
    };

    loadA(0, abuf[0]);

#pragma unroll 4
    for (int ks = 0; ks < 16; ks++) {
        const int buf = ks & 1;
        if (ks < 15) loadA(ks + 1, abuf[buf ^ 1]);   // overlap with mma

#pragma unroll
        for (int npq = 0; npq < 4; npq++) {
            const uint4 b4 = __ldg(B4 + (((size_t)(nppb + npq) * 16 + ks) * 32 + lane));
#pragma unroll
            for (int mt = 0; mt < 2; mt++) {
                const uint32_t* aF = reinterpret_cast<const uint32_t*>(&abuf[buf][mt]);
                mma_f16(acc[mt][npq * 2 + 0], aF, b4.x, b4.y);
                mma_f16(acc[mt][npq * 2 + 1], aF, b4.z, b4.w);
            }
        }
    }

    // ---- epilogue ----
#pragma unroll
    for (int mt = 0; mt < 2; mt++) {
        const int rA = n0 + warp_m + mt * 16 + gid;
        const int rB = rA + 8;
        const bool vA = rA < N_NODES;
        const bool vB = rB < N_NODES;
        float fA = 0.f, fB = 0.f;
        if (vA) fA = (off_at(rA + 1) - off_at(rA) > 0) ? 1.f : 0.f;
        if (vB) fB = (off_at(rB + 1) - off_at(rB) > 0) ? 1.f : 0.f;

#pragma unroll
        for (int nt = 0; nt < 8; nt++) {
            const int col = warp_n + nt * 8 + tig * 2;
            const float2 bnv = __ldg(reinterpret_cast<const float2*>(bn + col));
            const float2 bev = __ldg(reinterpret_cast<const float2*>(be + col));
            if (vA) {
                float2 o;
                o.x = acc[mt][nt][0] + bnv.x + fA * bev.x;
                o.y = acc[mt][nt][1] + bnv.y + fA * bev.y;
                *reinterpret_cast<float2*>(out + (size_t)rA * 128 + col) = o;
            }
            if (vB) {
                float2 o;
                o.x = acc[mt][nt][2] + bnv.x + fB * bev.x;
                o.y = acc[mt][nt][3] + bnv.y + fB * bev.y;
                *reinterpret_cast<float2*>(out + (size_t)rB * 128 + col) = o;
            }
        }
    }
}

// ---------------------------------------------------------------------------
extern "C" void kernel_launch(void* const* d_in, const int* in_sizes, int n_in,
                              void* d_out, int out_size) {
    const float* nfeat = (const float*)d_in[0];
    const float* efeat = (const float*)d_in[1];
    const float* ew    = (const float*)d_in[2];
    const float* Wn    = (const float*)d_in[3];
    const float* bn    = (const float*)d_in[4];
    const float* We    = (const float*)d_in[5];
    const float* be    = (const float*)d_in[6];
    const int*   src   = (const int*)d_in[7];
    const int*   dst   = (const int*)d_in[8];
    float*       out   = (float*)d_out;

    (void)in_sizes; (void)n_in; (void)out_size;

    k_setup <<<(N_NODES * 32 + 255) / 256, 256>>>(nfeat, dst, Wn, We);
    k_hist  <<<(N_EDGES + 255) / 256, 256>>>(dst);
    k_scan1 <<<N_SCAN_BLOCKS, SCAN_BLK>>>();
    k_perm  <<<(N_EDGES + 255) / 256, 256>>>(src, dst, ew);
    k_gather<<<N_PANELS, 512>>>(efeat);
    k_mgemm <<<(N_NODES + 127) / 128, 256>>>(bn, be, out);
}

// round 17
// speedup vs baseline: 1.1105x; 1.1105x over previous
#include <cuda_runtime.h>
#include <cuda_fp16.h>
#include <cstdint>

#define N_NODES 100000
#define N_EDGES 1600000
#define D 128
#define N_PANELS (N_NODES / 16)          // 6250, exact
#define SCAN_BLK 1024
#define N_SCAN_BLOCKS ((N_NODES + SCAN_BLK - 1) / SCAN_BLK)   // 98
#define EQ (N_EDGES / 4)                 // 400000

// ---------------------------------------------------------------------------
// Device scratch
// ---------------------------------------------------------------------------
__device__ int    g_cnt [N_NODES];
__device__ int    g_cur [N_NODES];
__device__ int    g_off [N_NODES + 1];
__device__ int    g_bsum[128];
__device__ float4 g_edata[N_EDGES];      // {eid, src, w, pad}
__device__ __half g_nh [(size_t)N_NODES * D];   // nfeat fp16 (25.6 MB)
// A in mma-fragment layout (fp16): [panel][ks(16)][lane(32)] -> uint4
__device__ uint4  g_xh4[(size_t)N_PANELS * 512];
// W in fragment layout (fp16): [npp(8)][ks(16)][lane(32)][word(4)]
__device__ uint32_t g_wh32[16384];

// ---------------------------------------------------------------------------
// helpers
// ---------------------------------------------------------------------------
__device__ __forceinline__ uint32_t hpair(float a, float b) {
    __half2 t = __floats2half2_rn(a, b);
    return *reinterpret_cast<uint32_t*>(&t);
}
__device__ __forceinline__ float4 h4_to_f4(uint2 h) {
    float2 a = __half22float2(*reinterpret_cast<__half2*>(&h.x));
    float2 b = __half22float2(*reinterpret_cast<__half2*>(&h.y));
    return make_float4(a.x, a.y, b.x, b.y);
}
__device__ __forceinline__ void mma_f16(float* d, const uint32_t* a,
                                        uint32_t b0, uint32_t b1) {
    asm volatile(
        "mma.sync.aligned.m16n8k16.row.col.f32.f16.f16.f32 "
        "{%0,%1,%2,%3}, {%4,%5,%6,%7}, {%8,%9}, {%0,%1,%2,%3};"
        : "+f"(d[0]), "+f"(d[1]), "+f"(d[2]), "+f"(d[3])
        : "r"(a[0]), "r"(a[1]), "r"(a[2]), "r"(a[3]), "r"(b0), "r"(b1));
}

// ---------------------------------------------------------------------------
// Setup kernels
// ---------------------------------------------------------------------------
// zero counters + convert nfeat -> fp16 (one pass)
__global__ __launch_bounds__(256) void k_nsplit(const float* __restrict__ nf) {
    const int i = blockIdx.x * blockDim.x + threadIdx.x;   // 0 .. 3.2M-1
    if (i < N_NODES) { g_cnt[i] = 0; g_cur[i] = 0; }
    if (i < N_NODES * (D / 4)) {
        const float4 v = __ldg(reinterpret_cast<const float4*>(nf) + i);
        uint2 h;
        h.x = hpair(v.x, v.y);
        h.y = hpair(v.z, v.w);
        reinterpret_cast<uint2*>(g_nh)[i] = h;
    }
}

// histogram: 4 edges/thread for MLP (strided, coalesced index loads)
__global__ __launch_bounds__(256) void k_hist(const int* __restrict__ dst) {
    const int t = blockIdx.x * blockDim.x + threadIdx.x;
    if (t >= EQ) return;
    const int d0 = __ldg(dst + t);
    const int d1 = __ldg(dst + t + EQ);
    const int d2 = __ldg(dst + t + 2 * EQ);
    const int d3 = __ldg(dst + t + 3 * EQ);
    atomicAdd(&g_cnt[d0], 1);
    atomicAdd(&g_cnt[d1], 1);
    atomicAdd(&g_cnt[d2], 1);
    atomicAdd(&g_cnt[d3], 1);
}

__global__ __launch_bounds__(SCAN_BLK) void k_scan1() {
    __shared__ int warp_pfx[32];
    const int tid = threadIdx.x;
    const int i   = blockIdx.x * SCAN_BLK + tid;
    const int v   = (i < N_NODES) ? g_cnt[i] : 0;

    int x = v;
#pragma unroll
    for (int o = 1; o < 32; o <<= 1) {
        int y = __shfl_up_sync(0xffffffffu, x, o);
        if ((tid & 31) >= o) x += y;
    }
    if ((tid & 31) == 31) warp_pfx[tid >> 5] = x;
    __syncthreads();
    if (tid < 32) {
        int t = warp_pfx[tid];
        int s = t;
#pragma unroll
        for (int o = 1; o < 32; o <<= 1) {
            int y = __shfl_up_sync(0xffffffffu, s, o);
            if (tid >= o) s += y;
        }
        warp_pfx[tid] = s - t;
        if (tid == 31) g_bsum[blockIdx.x] = s;
    }
    __syncthreads();
    if (i < N_NODES) g_off[i] = (x - v) + warp_pfx[tid >> 5];
}

__global__ __launch_bounds__(128) void k_scan2() {
    __shared__ int s[128];
    const int tid = threadIdx.x;
    const int v = (tid < N_SCAN_BLOCKS) ? g_bsum[tid] : 0;
    s[tid] = v;
    __syncthreads();
#pragma unroll
    for (int o = 1; o < 128; o <<= 1) {
        int y = (tid >= o) ? s[tid - o] : 0;
        __syncthreads();
        s[tid] += y;
        __syncthreads();
    }
    if (tid < N_SCAN_BLOCKS) g_bsum[tid] = s[tid] - v;
}

__global__ void k_scan3() {
    int i = blockIdx.x * blockDim.x + threadIdx.x;
    if (i < N_NODES) g_off[i] += g_bsum[i >> 10];
    if (i == 0) g_off[N_NODES] = N_EDGES;
}

// permute: 4 edges/thread for MLP; batched loads -> batched atomics -> stores
__global__ __launch_bounds__(256) void k_perm(const int* __restrict__ src,
                                              const int* __restrict__ dst,
                                              const float* __restrict__ ew) {
    const int t = blockIdx.x * blockDim.x + threadIdx.x;
    if (t >= EQ) return;
    const int e0 = t, e1 = t + EQ, e2 = t + 2 * EQ, e3 = t + 3 * EQ;

    const int d0 = __ldg(dst + e0);
    const int d1 = __ldg(dst + e1);
    const int d2 = __ldg(dst + e2);
    const int d3 = __ldg(dst + e3);
    const int s0 = __ldg(src + e0);
    const int s1 = __ldg(src + e1);
    const int s2 = __ldg(src + e2);
    const int s3 = __ldg(src + e3);
    const float w0 = __ldg(ew + e0);
    const float w1 = __ldg(ew + e1);
    const float w2 = __ldg(ew + e2);
    const float w3 = __ldg(ew + e3);

    const int b0 = __ldg(g_off + d0);
    const int b1 = __ldg(g_off + d1);
    const int b2 = __ldg(g_off + d2);
    const int b3 = __ldg(g_off + d3);

    const int p0 = b0 + atomicAdd(&g_cur[d0], 1);
    const int p1 = b1 + atomicAdd(&g_cur[d1], 1);
    const int p2 = b2 + atomicAdd(&g_cur[d2], 1);
    const int p3 = b3 + atomicAdd(&g_cur[d3], 1);

    g_edata[p0] = make_float4(__int_as_float(e0), __int_as_float(s0), w0, 0.f);
    g_edata[p1] = make_float4(__int_as_float(e1), __int_as_float(s1), w1, 0.f);
    g_edata[p2] = make_float4(__int_as_float(e2), __int_as_float(s2), w2, 0.f);
    g_edata[p3] = make_float4(__int_as_float(e3), __int_as_float(s3), w3, 0.f);
}

// W -> fp16 directly in B-fragment layout
__global__ __launch_bounds__(256) void k_wsplit(const float* __restrict__ Wn,
                                                const float* __restrict__ We) {
    const int idx = blockIdx.x * blockDim.x + threadIdx.x;  // 0..16383
    if (idx >= 16384) return;
    const int e    = idx >> 2;
    const int word = idx & 3;
    const int npp  = e >> 9;
    const int rem  = e & 511;
    const int ks   = rem >> 5;
    const int lane = rem & 31;
    const int gid  = lane >> 2;
    const int tig  = lane & 3;
    const int col  = npp * 16 + (word >> 1) * 8 + gid;
    const int k    = ks * 16 + (word & 1) * 8 + tig * 2;

    float v0, v1;
    if (k < 128) { v0 = __ldg(Wn + col * 128 + k);       v1 = __ldg(Wn + col * 128 + k + 1); }
    else         { v0 = __ldg(We + col * 128 + k - 128); v1 = __ldg(We + col * 128 + k - 127); }

    g_wh32[idx] = hpair(v0, v1);
}

// ---------------------------------------------------------------------------
// Gather: 512 threads = 16 warps = 1 panel (16 nodes). Warp w gathers node
// blockIdx.x*16+w. nfeat from fp16 copy; efeat streamed fp32.
// ---------------------------------------------------------------------------
__global__ __launch_bounds__(512) void k_gather(const float* __restrict__ efeat) {
    __shared__ uint32_t h32[16][132];

    const int tid  = threadIdx.x;
    const int w    = tid >> 5;
    const int lane = tid & 31;
    const int pan  = blockIdx.x;
    const int n    = pan * 16 + w;            // always < N_NODES

    const int beg = __ldg(g_off + n);
    const int end = __ldg(g_off + n + 1);

    float4 accn = make_float4(0.f, 0.f, 0.f, 0.f);
    float4 acce = make_float4(0.f, 0.f, 0.f, 0.f);

    const uint2* nh2 = reinterpret_cast<const uint2*>(g_nh);

    int i = beg;
    for (; i + 3 < end; i += 4) {
        const float4 p0 = __ldg(g_edata + i + 0);
        const float4 p1 = __ldg(g_edata + i + 1);
        const float4 p2 = __ldg(g_edata + i + 2);
        const float4 p3 = __ldg(g_edata + i + 3);
        const int e0 = __float_as_int(p0.x), s0 = __float_as_int(p0.y);
        const int e1 = __float_as_int(p1.x), s1 = __float_as_int(p1.y);
        const int e2 = __float_as_int(p2.x), s2 = __float_as_int(p2.y);
        const int e3 = __float_as_int(p3.x), s3 = __float_as_int(p3.y);
        const float w0 = p0.z, w1 = p1.z, w2 = p2.z, w3 = p3.z;

        const float4 f0 = __ldg(reinterpret_cast<const float4*>(efeat + (size_t)e0 * D) + lane);
        const float4 f1 = __ldg(reinterpret_cast<const float4*>(efeat + (size_t)e1 * D) + lane);
        const float4 f2 = __ldg(reinterpret_cast<const float4*>(efeat + (size_t)e2 * D) + lane);
        const float4 f3 = __ldg(reinterpret_cast<const float4*>(efeat + (size_t)e3 * D) + lane);
        const uint2  h0 = __ldg(nh2 + (size_t)s0 * 32 + lane);
        const uint2  h1 = __ldg(nh2 + (size_t)s1 * 32 + lane);
        const uint2  h2 = __ldg(nh2 + (size_t)s2 * 32 + lane);
        const uint2  h3 = __ldg(nh2 + (size_t)s3 * 32 + lane);

        const float4 m0 = h4_to_f4(h0);
        const float4 m1 = h4_to_f4(h1);
        const float4 m2 = h4_to_f4(h2);
        const float4 m3 = h4_to_f4(h3);

        acce.x += (f0.x + f1.x) + (f2.x + f3.x);
        acce.y += (f0.y + f1.y) + (f2.y + f3.y);
        acce.z += (f0.z + f1.z) + (f2.z + f3.z);
        acce.w += (f0.w + f1.w) + (f2.w + f3.w);
        accn.x += (w0 * m0.x + w1 * m1.x) + (w2 * m2.x + w3 * m3.x);
        accn.y += (w0 * m0.y + w1 * m1.y) + (w2 * m2.y + w3 * m3.y);
        accn.z += (w0 * m0.z + w1 * m1.z) + (w2 * m2.z + w3 * m3.z);
        accn.w += (w0 * m0.w + w1 * m1.w) + (w2 * m2.w + w3 * m3.w);
    }
    for (; i < end; i++) {
        const float4 p = __ldg(g_edata + i);
        const int e = __float_as_int(p.x), s = __float_as_int(p.y);
        const float wt = p.z;
        const float4 f  = __ldg(reinterpret_cast<const float4*>(efeat + (size_t)e * D) + lane);
        const float4 mm = h4_to_f4(__ldg(nh2 + (size_t)s * 32 + lane));
        acce.x += f.x; acce.y += f.y; acce.z += f.z; acce.w += f.w;
        accn.x += wt * mm.x; accn.y += wt * mm.y; accn.z += wt * mm.z; accn.w += wt * mm.w;
    }

    const float deg = (float)(end - beg);
    const float rd1 = 1.f / (deg + 1.f);
    const float rd2 = 1.f / fmaxf(deg, 1.f);

    const float4 self = h4_to_f4(__ldg(nh2 + (size_t)n * 32 + lane));
    float x1[4], x2[4];
    x1[0] = (accn.x + 2.f * self.x) * rd1;
    x1[1] = (accn.y + 2.f * self.y) * rd1;
    x1[2] = (accn.z + 2.f * self.z) * rd1;
    x1[3] = (accn.w + 2.f * self.w) * rd1;
    x2[0] = acce.x * rd2; x2[1] = acce.y * rd2;
    x2[2] = acce.z * rd2; x2[3] = acce.w * rd2;

    {
        uint2 a;
        a.x = hpair(x1[0], x1[1]);  a.y = hpair(x1[2], x1[3]);
        *reinterpret_cast<uint2*>(&h32[w][2 * lane]) = a;
        uint2 b;
        b.x = hpair(x2[0], x2[1]);  b.y = hpair(x2[2], x2[3]);
        *reinterpret_cast<uint2*>(&h32[w][64 + 2 * lane]) = b;
    }
    __syncthreads();

    {
        const int ks  = w;
        const int gid = lane >> 2;
        const int tig = lane & 3;
        uint4 vh;
        vh.x = h32[gid    ][ks * 8 + tig];
        vh.y = h32[gid + 8][ks * 8 + tig];
        vh.z = h32[gid    ][ks * 8 + 4 + tig];
        vh.w = h32[gid + 8][ks * 8 + 4 + tig];
        const size_t eidx = ((size_t)pan * 16 + ks) * 32 + lane;
        g_xh4[eidx] = vh;
    }
}

// ---------------------------------------------------------------------------
// fp16 HMMA GEMM, single pass. 256 threads = 8 warps.
// Block: 128 rows (8 panels) x 128 cols. Warp tile 32(M) x 64(N).
// ---------------------------------------------------------------------------
__global__ __launch_bounds__(256) void k_mgemm(const float* __restrict__ bn,
                                               const float* __restrict__ be,
                                               float* __restrict__ out) {
    const int bx   = blockIdx.x;
    const int tid  = threadIdx.x;
    const int w    = tid >> 5;
    const int lane = tid & 31;
    const int gid  = lane >> 2;
    const int tig  = lane & 3;
    const int warp_m = (w & 3) * 32;
    const int warp_n = (w >> 2) * 64;
    const int n0   = bx * 128;
    const int nppb = (w >> 2) * 4;

    float acc[2][8][4];
#pragma unroll
    for (int mt = 0; mt < 2; mt++)
#pragma unroll
        for (int nt = 0; nt < 8; nt++)
#pragma unroll
            for (int j = 0; j < 4; j++) acc[mt][nt][j] = 0.f;

    int  pan[2];
    bool pv[2];
#pragma unroll
    for (int mt = 0; mt < 2; mt++) {
        pan[mt] = bx * 8 + (w & 3) * 2 + mt;
        pv[mt]  = pan[mt] < N_PANELS;
    }

    const uint4* B4 = reinterpret_cast<const uint4*>(g_wh32);

    uint4 abuf[2][2];   // [buf][mt]
    auto loadA = [&](int ks, uint4* a_) {
#pragma unroll
        for (int mt = 0; mt < 2; mt++) {
            a_[mt] = make_uint4(0, 0, 0, 0);
            if (pv[mt])
                a_[mt] = __ldg(g_xh4 + ((size_t)(pan[mt] * 16 + ks) * 32 + lane));
        }
    };

    loadA(0, abuf[0]);

#pragma unroll 4
    for (int ks = 0; ks < 16; ks++) {
        const int buf = ks & 1;
        if (ks < 15) loadA(ks + 1, abuf[buf ^ 1]);   // overlap with mma

#pragma unroll
        for (int npq = 0; npq < 4; npq++) {
            const uint4 b4 = __ldg(B4 + (((size_t)(nppb + npq) * 16 + ks) * 32 + lane));
#pragma unroll
            for (int mt = 0; mt < 2; mt++) {
                const uint32_t* aF = reinterpret_cast<const uint32_t*>(&abuf[buf][mt]);
                mma_f16(acc[mt][npq * 2 + 0], aF, b4.x, b4.y);
                mma_f16(acc[mt][npq * 2 + 1], aF, b4.z, b4.w);
            }
        }
    }

    // ---- epilogue ----
#pragma unroll
    for (int mt = 0; mt < 2; mt++) {
        const int rA = n0 + warp_m + mt * 16 + gid;
        const int rB = rA + 8;
        const bool vA = rA < N_NODES;
        const bool vB = rB < N_NODES;
        float fA = 0.f, fB = 0.f;
        if (vA) fA = (__ldg(g_off + rA + 1) - __ldg(g_off + rA) > 0) ? 1.f : 0.f;
        if (vB) fB = (__ldg(g_off + rB + 1) - __ldg(g_off + rB) > 0) ? 1.f : 0.f;

#pragma unroll
        for (int nt = 0; nt < 8; nt++) {
            const int col = warp_n + nt * 8 + tig * 2;
            const float2 bnv = __ldg(reinterpret_cast<const float2*>(bn + col));
            const float2 bev = __ldg(reinterpret_cast<const float2*>(be + col));
            if (vA) {
                float2 o;
                o.x = acc[mt][nt][0] + bnv.x + fA * bev.x;
                o.y = acc[mt][nt][1] + bnv.y + fA * bev.y;
                *reinterpret_cast<float2*>(out + (size_t)rA * 128 + col) = o;
            }
            if (vB) {
                float2 o;
                o.x = acc[mt][nt][2] + bnv.x + fB * bev.x;
                o.y = acc[mt][nt][3] + bnv.y + fB * bev.y;
                *reinterpret_cast<float2*>(out + (size_t)rB * 128 + col) = o;
            }
        }
    }
}

// ---------------------------------------------------------------------------
extern "C" void kernel_launch(void* const* d_in, const int* in_sizes, int n_in,
                              void* d_out, int out_size) {
    const float* nfeat = (const float*)d_in[0];
    const float* efeat = (const float*)d_in[1];
    const float* ew    = (const float*)d_in[2];
    const float* Wn    = (const float*)d_in[3];
    const float* bn    = (const float*)d_in[4];
    const float* We    = (const float*)d_in[5];
    const float* be    = (const float*)d_in[6];
    const int*   src   = (const int*)d_in[7];
    const int*   dst   = (const int*)d_in[8];
    float*       out   = (float*)d_out;

    (void)in_sizes; (void)n_in; (void)out_size;

    k_nsplit<<<(N_NODES * 32 + 255) / 256, 256>>>(nfeat);   // zero + nfeat->fp16
    k_wsplit<<<64, 256>>>(Wn, We);
    k_hist  <<<(EQ + 255) / 256, 256>>>(dst);
    k_scan1 <<<N_SCAN_BLOCKS, SCAN_BLK>>>();
    k_scan2 <<<1, 128>>>();
    k_scan3 <<<(N_NODES + 255) / 256, 256>>>();
    k_perm  <<<(EQ + 255) / 256, 256>>>(src, dst, ew);
    k_gather<<<N_PANELS, 512>>>(efeat);
    k_mgemm <<<(N_NODES + 127) / 128, 256>>>(bn, be, out);
}